// round 5
// baseline (speedup 1.0000x reference)
#include <cuda_runtime.h>
#include <math_constants.h>

// Erosion2d: 3x3 min-pool, stride 1, +1e9 pad == +INF identity.
// x: [16,64,256,256] f32 -> out same shape.
//
// One warp covers full W=256 of R=4 consecutive rows (lane l: cols [8l,8l+7]).
// All 6 input rows loaded up-front (12 independent LDG.128, MLP=12).
// Vertical min via overlapping pairwise mins (idempotent min allows overlap):
//   m_i = min(r_i, r_{i+1}),  v_i = min(m_i, m_{i+1}).
// Horizontal halo via warp shuffle of the vertical-min vector.

#define H 256
#define W4 64          // row width in float4 units
#define R 4            // output rows per warp
#define TILES (H / R)  // 64 row-tiles per plane
#define NIMG 1024      // 16*64 planes

__device__ __forceinline__ float min3f(float a, float b, float c) {
    return fminf(fminf(a, b), c);
}
__device__ __forceinline__ float4 min2v(const float4& a, const float4& b) {
    return make_float4(fminf(a.x, b.x), fminf(a.y, b.y),
                       fminf(a.z, b.z), fminf(a.w, b.w));
}

__global__ void __launch_bounds__(256, 5)
erosion3x3_b5_kernel(const float4* __restrict__ x, float4* __restrict__ out) {
    const int gwarp = (blockIdx.x * blockDim.x + threadIdx.x) >> 5;
    const int lane  = threadIdx.x & 31;

    const int tile = gwarp & (TILES - 1);
    const int img  = gwarp >> 6;          // gwarp / TILES (TILES == 64)
    const int row0 = tile * R;

    // base (float4 units): img*H*W4 + row0*W4 + lane*2
    const size_t base = ((size_t)img << 14) + ((size_t)row0 << 6) + ((size_t)lane << 1);
    const float4* p = x + base;
    float4* po = out + base;

    const float4 INF4 = make_float4(CUDART_INF_F, CUDART_INF_F, CUDART_INF_F, CUDART_INF_F);

    // Front-batched loads: rows row0-1 .. row0+4  (6 rows x 2 float4 = 12 LDG.128)
    float4 w[6][2];
    const bool top = (row0 == 0);
    const bool bot = (row0 + R == H);

    w[1][0] = p[0 * W4];     w[1][1] = p[0 * W4 + 1];
    w[2][0] = p[1 * W4];     w[2][1] = p[1 * W4 + 1];
    w[3][0] = p[2 * W4];     w[3][1] = p[2 * W4 + 1];
    w[4][0] = p[3 * W4];     w[4][1] = p[3 * W4 + 1];
    if (!top) { w[0][0] = p[-W4];    w[0][1] = p[-W4 + 1]; }
    else      { w[0][0] = INF4;      w[0][1] = INF4; }
    if (!bot) { w[5][0] = p[4 * W4]; w[5][1] = p[4 * W4 + 1]; }
    else      { w[5][0] = INF4;      w[5][1] = INF4; }

    // Overlapping pairwise row mins: m[i] = min(row i, row i+1), i=0..4
    float4 m[5][2];
    #pragma unroll
    for (int i = 0; i < 5; i++) {
        m[i][0] = min2v(w[i][0], w[i + 1][0]);
        m[i][1] = min2v(w[i][1], w[i + 1][1]);
    }

    #pragma unroll
    for (int i = 0; i < R; i++) {
        // vertical 3-row min = min of two overlapping pair-mins
        float4 v0 = min2v(m[i][0], m[i + 1][0]);
        float4 v1 = min2v(m[i][1], m[i + 1][1]);

        // horizontal halos via shuffle of the vertical-min vector
        float l = __shfl_up_sync(0xffffffffu, v1.w, 1);    // left nbr's col 8l-1
        float r = __shfl_down_sync(0xffffffffu, v0.x, 1);  // right nbr's col 8l+8
        if (lane == 0)  l = CUDART_INF_F;
        if (lane == 31) r = CUDART_INF_F;

        float4 o0, o1;
        o0.x = min3f(l,    v0.x, v0.y);
        o0.y = min3f(v0.x, v0.y, v0.z);
        o0.z = min3f(v0.y, v0.z, v0.w);
        o0.w = min3f(v0.z, v0.w, v1.x);
        o1.x = min3f(v0.w, v1.x, v1.y);
        o1.y = min3f(v1.x, v1.y, v1.z);
        o1.z = min3f(v1.y, v1.z, v1.w);
        o1.w = min3f(v1.z, v1.w, r);

        float4* qo = po + (size_t)i * W4;
        qo[0] = o0; qo[1] = o1;
    }
}

extern "C" void kernel_launch(void* const* d_in, const int* in_sizes, int n_in,
                              void* d_out, int out_size) {
    const float4* x = (const float4*)d_in[0];
    float4* out = (float4*)d_out;
    // warps = NIMG * TILES = 1024*64 = 65536 -> 8192 blocks of 256 threads
    const int threads = 256;
    const int blocks  = (NIMG * TILES * 32) / threads;
    erosion3x3_b5_kernel<<<blocks, threads>>>(x, out);
}